// round 1
// baseline (speedup 1.0000x reference)
#include <cuda_runtime.h>

#define HID 256
#define G4  1024
#define NE  64
#define BAT 256
#define NSTEP 6
#define RK  16

// ---------------- scratch (allocation-free: device globals) ----------------
__device__ float g_xg[NE * G4];     // x@Wih^T + bih + bhh  (step-invariant)
__device__ float g_h0[NE * HID];
__device__ float g_c0[NE * HID];
__device__ float g_h[BAT * HID];    // doubles as hsel
__device__ float g_c[BAT * HID];    // doubles as csel
__device__ float g_hg[BAT * G4];    // h @ Whh^T
__device__ float g_hsum[BAT * HID]; // sum_j hn[b,j,:]
__device__ float g_total[BAT * RK];

// ---------------- fast-but-accurate transcendentals (ex2/rcp, ~1e-6 rel) ---
__device__ __forceinline__ float fex2(float x){ float y; asm("ex2.approx.f32 %0, %1;" : "=f"(y) : "f"(x)); return y; }
__device__ __forceinline__ float frcp(float x){ float y; asm("rcp.approx.f32 %0, %1;" : "=f"(y) : "f"(x)); return y; }
__device__ __forceinline__ float sigm(float x){ return frcp(1.0f + fex2(-1.4426950408889634f * x)); }
__device__ __forceinline__ float tanh_(float x){ return fmaf(-2.0f, frcp(1.0f + fex2(2.8853900817779268f * x)), 1.0f); }

// ============================================================================
// K0: xg[j][m] = emb[j] . Wih[m] + bih[m] + bhh[m]; also h0,c0 = cell(xg, c=0)
// grid = 64 (one block per emb row j), 256 threads (k / output lane)
// Thread t accumulates the 4 gate rows {t, 256+t, 512+t, 768+t}, which are
// exactly the 4 gates of hidden index k=t -> h0/c0 computed in-register.
// ============================================================================
__global__ __launch_bounds__(256) void k_init(const float* __restrict__ emb,
                                              const float* __restrict__ Wih,
                                              const float* __restrict__ bih,
                                              const float* __restrict__ bhh)
{
    __shared__ float es[HID];
    const int j = blockIdx.x, t = threadIdx.x;
    es[t] = emb[j * HID + t];
    __syncthreads();

    const float4* w0 = (const float4*)(Wih + (0 * HID + t) * HID);
    const float4* w1 = (const float4*)(Wih + (1 * HID + t) * HID);
    const float4* w2 = (const float4*)(Wih + (2 * HID + t) * HID);
    const float4* w3 = (const float4*)(Wih + (3 * HID + t) * HID);

    float a0 = 0.f, a1 = 0.f, a2 = 0.f, a3 = 0.f;
    #pragma unroll 4
    for (int q = 0; q < HID / 4; q++) {
        const float e0 = es[4*q+0], e1 = es[4*q+1], e2 = es[4*q+2], e3 = es[4*q+3];
        float4 v;
        v = w0[q]; a0 = fmaf(e0, v.x, fmaf(e1, v.y, fmaf(e2, v.z, fmaf(e3, v.w, a0))));
        v = w1[q]; a1 = fmaf(e0, v.x, fmaf(e1, v.y, fmaf(e2, v.z, fmaf(e3, v.w, a1))));
        v = w2[q]; a2 = fmaf(e0, v.x, fmaf(e1, v.y, fmaf(e2, v.z, fmaf(e3, v.w, a2))));
        v = w3[q]; a3 = fmaf(e0, v.x, fmaf(e1, v.y, fmaf(e2, v.z, fmaf(e3, v.w, a3))));
    }
    a0 += bih[0*HID+t] + bhh[0*HID+t];
    a1 += bih[1*HID+t] + bhh[1*HID+t];
    a2 += bih[2*HID+t] + bhh[2*HID+t];
    a3 += bih[3*HID+t] + bhh[3*HID+t];

    g_xg[j*G4 + 0*HID + t] = a0;
    g_xg[j*G4 + 1*HID + t] = a1;
    g_xg[j*G4 + 2*HID + t] = a2;
    g_xg[j*G4 + 3*HID + t] = a3;

    const float c0 = sigm(a0) * tanh_(a2);       // f*0 + i*g
    const float h0 = sigm(a3) * tanh_(c0);
    g_c0[j*HID + t] = c0;
    g_h0[j*HID + t] = h0;
}

// ============================================================================
// K1 (single block): out0 = h0@Wf^T + bf, column-normalize over j, gather
// total/h/c by idx[0].
// ============================================================================
__global__ __launch_bounds__(256) void k_step0(const float* __restrict__ Wf,
                                               const float* __restrict__ bf,
                                               const int* __restrict__ xidx)
{
    __shared__ float sout[NE * RK];
    __shared__ float rcol[RK];
    const int t = threadIdx.x;

    #pragma unroll
    for (int p = 0; p < 4; p++) {
        const int e = t + 256 * p;         // 0..1023 -> (j, r)
        const int j = e >> 4, r = e & 15;
        const float* hr = g_h0 + j * HID;
        const float* wr = Wf + r * HID;
        float acc = 0.f;
        #pragma unroll 8
        for (int k = 0; k < HID; k++) acc = fmaf(hr[k], wr[k], acc);
        sout[j * RK + r] = acc + bf[r];
    }
    __syncthreads();
    if (t < RK) {
        float s = 0.f;
        for (int j = 0; j < NE; j++) s += sout[j * RK + t];
        rcol[t] = 1.0f / s;
    }
    __syncthreads();
    {   // thread t == batch b
        const int sel = xidx[t * NSTEP + 0];
        #pragma unroll
        for (int r = 0; r < RK; r++)
            g_total[t * RK + r] = sout[sel * RK + r] * rcol[r];
    }
    for (int b = 0; b < BAT; b++) {        // warp-uniform b -> coalesced
        const int sel = xidx[b * NSTEP + 0];
        g_h[b * HID + t] = g_h0[sel * HID + t];
        g_c[b * HID + t] = g_c0[sel * HID + t];
    }
}

// ============================================================================
// K2: hg[256][1024] = h[256][256] @ Whh^T.  Tiled SGEMM, BM=32 BN=64 BK=16,
// grid (8,16)=128 blocks, 256 threads, 2x4 microtile.
// ============================================================================
#define BM 32
#define BN 64
#define BK 16
__global__ __launch_bounds__(256) void k_hg(const float* __restrict__ Whh)
{
    __shared__ float As[BM][BK + 1];
    __shared__ float Bs[BN][BK + 1];
    const int t = threadIdx.x;
    const int tx = t & 15, ty = t >> 4;
    const int b0 = blockIdx.x * BM;
    const int m0 = blockIdx.y * BN;
    float acc[2][4] = {};

    for (int k0 = 0; k0 < HID; k0 += BK) {
        if (t < 128) {
            const int ar = t >> 2, ac = (t & 3) * 4;
            const float4 v = *(const float4*)&g_h[(b0 + ar) * HID + k0 + ac];
            As[ar][ac+0] = v.x; As[ar][ac+1] = v.y; As[ar][ac+2] = v.z; As[ar][ac+3] = v.w;
        }
        {
            const int br = t >> 2, bc = (t & 3) * 4;
            const float4 v = *(const float4*)&Whh[(m0 + br) * HID + k0 + bc];
            Bs[br][bc+0] = v.x; Bs[br][bc+1] = v.y; Bs[br][bc+2] = v.z; Bs[br][bc+3] = v.w;
        }
        __syncthreads();
        #pragma unroll
        for (int kk = 0; kk < BK; kk++) {
            const float a0 = As[2*ty+0][kk], a1 = As[2*ty+1][kk];
            const float q0 = Bs[4*tx+0][kk], q1 = Bs[4*tx+1][kk];
            const float q2 = Bs[4*tx+2][kk], q3 = Bs[4*tx+3][kk];
            acc[0][0] = fmaf(a0,q0,acc[0][0]); acc[0][1] = fmaf(a0,q1,acc[0][1]);
            acc[0][2] = fmaf(a0,q2,acc[0][2]); acc[0][3] = fmaf(a0,q3,acc[0][3]);
            acc[1][0] = fmaf(a1,q0,acc[1][0]); acc[1][1] = fmaf(a1,q1,acc[1][1]);
            acc[1][2] = fmaf(a1,q2,acc[1][2]); acc[1][3] = fmaf(a1,q3,acc[1][3]);
        }
        __syncthreads();
    }
    #pragma unroll
    for (int i = 0; i < 2; i++)
        #pragma unroll
        for (int jj = 0; jj < 4; jj++)
            g_hg[(b0 + 2*ty + i) * G4 + m0 + 4*tx + jj] = acc[i][jj];
}

// ============================================================================
// K3: LSTM cell over all (b, j): hsum = sum_j hn; hsel/csel at j==idx[step].
// grid 256 (one b per block), 256 threads (k).
// ============================================================================
__global__ __launch_bounds__(256) void k_cell(const int* __restrict__ xidx, int step)
{
    const int b = blockIdx.x, t = threadIdx.x;
    const int sel = xidx[b * NSTEP + step];
    const float* __restrict__ hg = g_hg + b * G4;
    const float hgi = hg[t], hgf = hg[HID + t], hgg = hg[2*HID + t], hgo = hg[3*HID + t];
    const float cp = g_c[b * HID + t];
    float hs = 0.f, hselv = 0.f, cselv = 0.f;

    #pragma unroll 8
    for (int j = 0; j < NE; j++) {
        const float* __restrict__ xr = g_xg + j * G4;
        const float gi = xr[t]         + hgi;
        const float gf = xr[HID + t]   + hgf;
        const float gg = xr[2*HID + t] + hgg;
        const float go = xr[3*HID + t] + hgo;
        const float iv = sigm(gi), fv = sigm(gf);
        const float gv = tanh_(gg),  ov = sigm(go);
        const float cn = fmaf(fv, cp, iv * gv);
        const float hn = ov * tanh_(cn);
        hs += hn;
        if (j == sel) { hselv = hn; cselv = cn; }
    }
    g_hsum[b * HID + t] = hs;
    g_h[b * HID + t]    = hselv;   // next h
    g_c[b * HID + t]    = cselv;   // next c
}

// ============================================================================
// K4 (middle steps): num=hsel@Wm^T+bm, den=hsum@Wm^T+64*bm, cur=num/den,
// total = total @ cur(16x16).  grid 128 (2 b per block), 256 threads (m).
// ============================================================================
__global__ __launch_bounds__(256) void k_mid(const float* __restrict__ Wm,
                                             const float* __restrict__ bm)
{
    __shared__ float sh[2][HID], ss[2][HID], scur[2][HID];
    __shared__ float stot[2][RK];
    const int t = threadIdx.x;
    const int b0 = blockIdx.x * 2;
    #pragma unroll
    for (int i = 0; i < 2; i++) {
        sh[i][t] = g_h[(b0 + i) * HID + t];
        ss[i][t] = g_hsum[(b0 + i) * HID + t];
    }
    if (t < 2 * RK) stot[t >> 4][t & 15] = g_total[b0 * RK + t];
    __syncthreads();

    const float4* wr = (const float4*)(Wm + t * HID);
    float n0 = 0.f, d0 = 0.f, n1 = 0.f, d1 = 0.f;
    #pragma unroll 4
    for (int q = 0; q < HID / 4; q++) {
        const float4 w = wr[q];
        const int k = 4 * q;
        n0 = fmaf(w.x, sh[0][k+0], fmaf(w.y, sh[0][k+1], fmaf(w.z, sh[0][k+2], fmaf(w.w, sh[0][k+3], n0))));
        d0 = fmaf(w.x, ss[0][k+0], fmaf(w.y, ss[0][k+1], fmaf(w.z, ss[0][k+2], fmaf(w.w, ss[0][k+3], d0))));
        n1 = fmaf(w.x, sh[1][k+0], fmaf(w.y, sh[1][k+1], fmaf(w.z, sh[1][k+2], fmaf(w.w, sh[1][k+3], n1))));
        d1 = fmaf(w.x, ss[1][k+0], fmaf(w.y, ss[1][k+1], fmaf(w.z, ss[1][k+2], fmaf(w.w, ss[1][k+3], d1))));
    }
    const float bmv = bm[t];
    scur[0][t] = (n0 + bmv) * frcp(d0 + 64.0f * bmv);
    scur[1][t] = (n1 + bmv) * frcp(d1 + 64.0f * bmv);
    __syncthreads();

    if (t < 2 * RK) {
        const int bl = t >> 4, r2 = t & 15;
        float acc = 0.f;
        #pragma unroll
        for (int r1 = 0; r1 < RK; r1++)
            acc = fmaf(stot[bl][r1], scur[bl][r1 * RK + r2], acc);
        g_total[(b0 + bl) * RK + r2] = acc;
    }
}

// ============================================================================
// K5 (final): cur = (hsel@Wl^T+bl)/(hsum@Wl^T+64*bl); out[b] = total[b].cur
// grid 32 (8 b per block), 256 threads: one warp per b; lanes 0..15 num rows,
// lanes 16..31 den rows.
// ============================================================================
__global__ __launch_bounds__(256) void k_final(const float* __restrict__ Wl,
                                               const float* __restrict__ blv,
                                               float* __restrict__ out)
{
    const int w = threadIdx.x >> 5, l = threadIdx.x & 31;
    const int b = blockIdx.x * 8 + w;
    const int r = l & 15;
    const float* __restrict__ hx = (l < 16) ? (g_h + b * HID) : (g_hsum + b * HID);
    const float* __restrict__ wr = Wl + r * HID;
    float acc = 0.f;
    #pragma unroll 8
    for (int k = 0; k < HID; k++) acc = fmaf(wr[k], hx[k], acc);
    acc += (l < 16 ? 1.0f : 64.0f) * blv[r];

    const float den = __shfl_down_sync(0xFFFFFFFFu, acc, 16);
    float v = 0.f;
    if (l < 16) v = g_total[b * RK + l] * acc * frcp(den);
    v += __shfl_xor_sync(0xFFFFFFFFu, v, 8);
    v += __shfl_xor_sync(0xFFFFFFFFu, v, 4);
    v += __shfl_xor_sync(0xFFFFFFFFu, v, 2);
    v += __shfl_xor_sync(0xFFFFFFFFu, v, 1);
    if (l == 0) out[b] = v;
}

// ============================================================================
extern "C" void kernel_launch(void* const* d_in, const int* in_sizes, int n_in,
                              void* d_out, int out_size)
{
    (void)in_sizes; (void)n_in; (void)out_size;
    const int*   x_idx = (const int*)  d_in[0];
    const float* emb   = (const float*)d_in[1];
    const float* Wih   = (const float*)d_in[2];
    const float* Whh   = (const float*)d_in[3];
    const float* bih   = (const float*)d_in[4];
    const float* bhh   = (const float*)d_in[5];
    const float* Wf    = (const float*)d_in[6];
    const float* bf    = (const float*)d_in[7];
    const float* Wm    = (const float*)d_in[8];
    const float* bm    = (const float*)d_in[9];
    const float* Wl    = (const float*)d_in[10];
    const float* bl    = (const float*)d_in[11];
    float* out = (float*)d_out;

    k_init <<<NE, 256>>>(emb, Wih, bih, bhh);
    k_step0<<<1, 256>>>(Wf, bf, x_idx);
    for (int s = 1; s < NSTEP - 1; s++) {
        k_hg  <<<dim3(BAT / BM, G4 / BN), 256>>>(Whh);
        k_cell<<<BAT, 256>>>(x_idx, s);
        k_mid <<<BAT / 2, 256>>>(Wm, bm);
    }
    k_hg   <<<dim3(BAT / BM, G4 / BN), 256>>>(Whh);
    k_cell <<<BAT, 256>>>(x_idx, NSTEP - 1);
    k_final<<<BAT / 8, 256>>>(Wl, bl, out);
}

// round 3
// speedup vs baseline: 1.1058x; 1.1058x over previous
#include <cuda_runtime.h>

#define HID 256
#define G4  1024
#define NE  64
#define BAT 256
#define NSTEP 6
#define RK  16

// ---------------- scratch (allocation-free: device globals) ----------------
__device__ float g_xg[NE * G4];        // gate-interleaved: [j][k][4 gates] (float4 per k)
__device__ float g_h0[NE * HID];
__device__ float g_c0[NE * HID];
__device__ float g_h[BAT * HID];       // hsel (next h)
__device__ float g_cb[2][BAT * HID];   // c ping-pong
__device__ float g_hgp[2][BAT * G4];   // h @ Whh^T, split-K partials
__device__ float g_hsp[4][BAT * HID];  // hsum partials per j-chunk
__device__ float g_total[BAT * RK];

// ---------------- transcendentals: single-MUFU tanh.approx -----------------
__device__ __forceinline__ float tap(float x){ float y; asm("tanh.approx.f32 %0,%1;" : "=f"(y) : "f"(x)); return y; }
__device__ __forceinline__ float frcp(float x){ float y; asm("rcp.approx.f32 %0,%1;" : "=f"(y) : "f"(x)); return y; }
__device__ __forceinline__ float sigm(float x){ return fmaf(0.5f, tap(0.5f * x), 0.5f); }

// ============================================================================
// K_initA: xg[j][m] = emb[j].Wih[m] + bih[m] + bhh[m], tiled GEMM.
// M=64(j) N=1024(m) K=256. BM=32 BN=64 BK=16, grid (2,16), 256 thr, 2x4 utile.
// Output written gate-interleaved: g_xg[j*1024 + 4*k + gate], gate=m>>8, k=m&255.
// ============================================================================
__global__ __launch_bounds__(256) void k_initA(const float* __restrict__ emb,
                                               const float* __restrict__ Wih,
                                               const float* __restrict__ bih,
                                               const float* __restrict__ bhh)
{
    __shared__ float As[16][34];
    __shared__ float Bs[16][68];
    const int t = threadIdx.x;
    const int tx = t & 15, ty = t >> 4;
    const int b0 = blockIdx.x * 32;
    const int m0 = blockIdx.y * 64;
    float acc[2][4] = {};

    for (int k0 = 0; k0 < HID; k0 += 16) {
        if (t < 128) {
            const int r = t >> 2, c = (t & 3) * 4;
            const float4 v = *(const float4*)&emb[(b0 + r) * HID + k0 + c];
            As[c+0][r] = v.x; As[c+1][r] = v.y; As[c+2][r] = v.z; As[c+3][r] = v.w;
        }
        {
            const int r = t >> 2, c = (t & 3) * 4;
            const float4 v = *(const float4*)&Wih[(m0 + r) * HID + k0 + c];
            Bs[c+0][r] = v.x; Bs[c+1][r] = v.y; Bs[c+2][r] = v.z; Bs[c+3][r] = v.w;
        }
        __syncthreads();
        #pragma unroll
        for (int kk = 0; kk < 16; kk++) {
            const float2 a = *(const float2*)&As[kk][2 * ty];
            const float4 bv = *(const float4*)&Bs[kk][4 * tx];
            acc[0][0] = fmaf(a.x, bv.x, acc[0][0]); acc[0][1] = fmaf(a.x, bv.y, acc[0][1]);
            acc[0][2] = fmaf(a.x, bv.z, acc[0][2]); acc[0][3] = fmaf(a.x, bv.w, acc[0][3]);
            acc[1][0] = fmaf(a.y, bv.x, acc[1][0]); acc[1][1] = fmaf(a.y, bv.y, acc[1][1]);
            acc[1][2] = fmaf(a.y, bv.z, acc[1][2]); acc[1][3] = fmaf(a.y, bv.w, acc[1][3]);
        }
        __syncthreads();
    }
    const int mc0 = m0 + 4 * tx;
    const int gate = mc0 >> 8;          // constant across the 4 cols
    const int kc0  = mc0 & 255;
    float bias[4];
    #pragma unroll
    for (int jj = 0; jj < 4; jj++) bias[jj] = bih[mc0 + jj] + bhh[mc0 + jj];
    #pragma unroll
    for (int i = 0; i < 2; i++) {
        const int jr = b0 + 2 * ty + i;
        #pragma unroll
        for (int jj = 0; jj < 4; jj++)
            g_xg[jr * G4 + 4 * (kc0 + jj) + gate] = acc[i][jj] + bias[jj];
    }
}

// ============================================================================
// K_init2: h0/c0 = cell(xg, c=0). grid 64, 256 thr.
// ============================================================================
__global__ __launch_bounds__(256) void k_init2()
{
    const int j = blockIdx.x, t = threadIdx.x;
    const float4 x4 = ((const float4*)g_xg)[j * HID + t];  // (i,f,g,o)
    const float c0 = sigm(x4.x) * tap(x4.z);
    const float h0 = sigm(x4.w) * tap(c0);
    g_c0[j * HID + t] = c0;
    g_h0[j * HID + t] = h0;
}

// ============================================================================
// K_step0 (single block): out0 = h0@Wf^T + bf, column-normalize over j,
// gather total/h/c by idx[0]. c written to ping-pong buf 1.
// ============================================================================
__global__ __launch_bounds__(256) void k_step0(const float* __restrict__ Wf,
                                               const float* __restrict__ bf,
                                               const int* __restrict__ xidx)
{
    __shared__ float sout[NE * RK];
    __shared__ float rcol[RK];
    const int t = threadIdx.x;

    #pragma unroll
    for (int p = 0; p < 4; p++) {
        const int e = t + 256 * p;
        const int j = e >> 4, r = e & 15;
        const float* hr = g_h0 + j * HID;
        const float* wr = Wf + r * HID;
        float acc = 0.f;
        #pragma unroll 8
        for (int k = 0; k < HID; k++) acc = fmaf(hr[k], wr[k], acc);
        sout[j * RK + r] = acc + bf[r];
    }
    __syncthreads();
    if (t < RK) {
        float s = 0.f;
        for (int j = 0; j < NE; j++) s += sout[j * RK + t];
        rcol[t] = 1.0f / s;
    }
    __syncthreads();
    {
        const int sel = xidx[t * NSTEP + 0];
        #pragma unroll
        for (int r = 0; r < RK; r++)
            g_total[t * RK + r] = sout[sel * RK + r] * rcol[r];
    }
    for (int b = 0; b < BAT; b++) {
        const int sel = xidx[b * NSTEP + 0];
        g_h[b * HID + t]       = g_h0[sel * HID + t];
        g_cb[1][b * HID + t]   = g_c0[sel * HID + t];
    }
}

// ============================================================================
// K_hgmid: z<2 -> hg split-K GEMM half z; z==2 -> mid(step-1) GEMV+total update.
// hg: 256x1024 = h @ Whh^T.  BM=32 BN=64 BK=16 KHALF=128, grid(8,16,·), 2x4 utile.
// mid: 128 slots x 2 b each: cur = (hsel@Wm^T+bm)/(hsum@Wm^T+64bm),
// total = total @ cur.  Both read g_h/g_hsp, no conflicts -> safe to merge.
// ============================================================================
__global__ __launch_bounds__(256) void k_hgmid(const float* __restrict__ Whh,
                                               const float* __restrict__ Wm,
                                               const float* __restrict__ bm,
                                               int do_mid)
{
    __shared__ union {
        struct { float As[16][34]; float Bs[16][68]; } g;
        struct { float sh[2][HID]; float ss[2][HID]; float scur[2][HID]; float stot[2][RK]; } m;
    } S;
    const int t = threadIdx.x;
    const int z = blockIdx.z;

    if (z < 2) {
        const int tx = t & 15, ty = t >> 4;
        const int b0 = blockIdx.x * 32;
        const int m0 = blockIdx.y * 64;
        const int kb = z * 128;
        float acc[2][4] = {};

        for (int k0 = 0; k0 < 128; k0 += 16) {
            if (t < 128) {
                const int r = t >> 2, c = (t & 3) * 4;
                const float4 v = *(const float4*)&g_h[(b0 + r) * HID + kb + k0 + c];
                S.g.As[c+0][r] = v.x; S.g.As[c+1][r] = v.y; S.g.As[c+2][r] = v.z; S.g.As[c+3][r] = v.w;
            }
            {
                const int r = t >> 2, c = (t & 3) * 4;
                const float4 v = *(const float4*)&Whh[(m0 + r) * HID + kb + k0 + c];
                S.g.Bs[c+0][r] = v.x; S.g.Bs[c+1][r] = v.y; S.g.Bs[c+2][r] = v.z; S.g.Bs[c+3][r] = v.w;
            }
            __syncthreads();
            #pragma unroll
            for (int kk = 0; kk < 16; kk++) {
                const float2 a = *(const float2*)&S.g.As[kk][2 * ty];
                const float4 bv = *(const float4*)&S.g.Bs[kk][4 * tx];
                acc[0][0] = fmaf(a.x, bv.x, acc[0][0]); acc[0][1] = fmaf(a.x, bv.y, acc[0][1]);
                acc[0][2] = fmaf(a.x, bv.z, acc[0][2]); acc[0][3] = fmaf(a.x, bv.w, acc[0][3]);
                acc[1][0] = fmaf(a.y, bv.x, acc[1][0]); acc[1][1] = fmaf(a.y, bv.y, acc[1][1]);
                acc[1][2] = fmaf(a.y, bv.z, acc[1][2]); acc[1][3] = fmaf(a.y, bv.w, acc[1][3]);
            }
            __syncthreads();
        }
        #pragma unroll
        for (int i = 0; i < 2; i++) {
            float4 o = make_float4(acc[i][0], acc[i][1], acc[i][2], acc[i][3]);
            *(float4*)&g_hgp[z][(b0 + 2 * ty + i) * G4 + m0 + 4 * tx] = o;
        }
    } else {
        if (!do_mid) return;
        const int b0 = (blockIdx.y * 8 + blockIdx.x) * 2;
        #pragma unroll
        for (int i = 0; i < 2; i++) {
            S.m.sh[i][t] = g_h[(b0 + i) * HID + t];
            S.m.ss[i][t] = g_hsp[0][(b0 + i) * HID + t] + g_hsp[1][(b0 + i) * HID + t]
                         + g_hsp[2][(b0 + i) * HID + t] + g_hsp[3][(b0 + i) * HID + t];
        }
        if (t < 2 * RK) S.m.stot[t >> 4][t & 15] = g_total[b0 * RK + t];
        __syncthreads();

        const float4* wr = (const float4*)(Wm + t * HID);
        float n0 = 0.f, d0 = 0.f, n1 = 0.f, d1 = 0.f;
        #pragma unroll 4
        for (int q = 0; q < HID / 4; q++) {
            const float4 w = wr[q];
            const float4 h0v = *(const float4*)&S.m.sh[0][4 * q];
            const float4 s0v = *(const float4*)&S.m.ss[0][4 * q];
            const float4 h1v = *(const float4*)&S.m.sh[1][4 * q];
            const float4 s1v = *(const float4*)&S.m.ss[1][4 * q];
            n0 = fmaf(w.x, h0v.x, fmaf(w.y, h0v.y, fmaf(w.z, h0v.z, fmaf(w.w, h0v.w, n0))));
            d0 = fmaf(w.x, s0v.x, fmaf(w.y, s0v.y, fmaf(w.z, s0v.z, fmaf(w.w, s0v.w, d0))));
            n1 = fmaf(w.x, h1v.x, fmaf(w.y, h1v.y, fmaf(w.z, h1v.z, fmaf(w.w, h1v.w, n1))));
            d1 = fmaf(w.x, s1v.x, fmaf(w.y, s1v.y, fmaf(w.z, s1v.z, fmaf(w.w, s1v.w, d1))));
        }
        const float bmv = bm[t];
        S.m.scur[0][t] = (n0 + bmv) * frcp(d0 + 64.0f * bmv);
        S.m.scur[1][t] = (n1 + bmv) * frcp(d1 + 64.0f * bmv);
        __syncthreads();

        if (t < 2 * RK) {
            const int bl = t >> 4, r2 = t & 15;
            float acc = 0.f;
            #pragma unroll
            for (int r1 = 0; r1 < RK; r1++)
                acc = fmaf(S.m.stot[bl][r1], S.m.scur[bl][r1 * RK + r2], acc);
            g_total[(b0 + bl) * RK + r2] = acc;
        }
    }
}

// ============================================================================
// K_cell: grid (128 b-pairs, 4 j-chunks), 256 thr (k). Each block processes
// j in [16*jc, 16*jc+16) for 2 batches sharing one xg float4 load per j.
// Writes per-chunk hsum partial; the sel-owning chunk writes h/c (c ping-pong).
// ============================================================================
__global__ __launch_bounds__(256) void k_cell(const int* __restrict__ xidx,
                                              int step, int pin, int pout)
{
    const int t = threadIdx.x;
    const int b0 = blockIdx.x * 2;
    const int jc = blockIdx.y;
    const int sel0 = xidx[(b0 + 0) * NSTEP + step];
    const int sel1 = xidx[(b0 + 1) * NSTEP + step];

    // front-batched partial-sum loads (grouped so ptxas issues them together)
    const float* __restrict__ p00 = g_hgp[0] + (b0 + 0) * G4 + t;
    const float* __restrict__ p10 = g_hgp[1] + (b0 + 0) * G4 + t;
    const float* __restrict__ p01 = g_hgp[0] + (b0 + 1) * G4 + t;
    const float* __restrict__ p11 = g_hgp[1] + (b0 + 1) * G4 + t;
    const float a00 = p00[0],      a01 = p00[HID],  a02 = p00[2*HID], a03 = p00[3*HID];
    const float b00 = p10[0],      b01 = p10[HID],  b02 = p10[2*HID], b03 = p10[3*HID];
    const float a10 = p01[0],      a11 = p01[HID],  a12 = p01[2*HID], a13 = p01[3*HID];
    const float b10 = p11[0],      b11 = p11[HID],  b12 = p11[2*HID], b13 = p11[3*HID];
    const float cp0 = g_cb[pin][(b0+0) * HID + t];
    const float cp1 = g_cb[pin][(b0+1) * HID + t];

    const float hgi0 = a00 + b00, hgf0 = a01 + b01, hgg0 = a02 + b02, hgo0 = a03 + b03;
    const float hgi1 = a10 + b10, hgf1 = a11 + b11, hgg1 = a12 + b12, hgo1 = a13 + b13;

    float hs0 = 0.f, hs1 = 0.f;
    float hsel0 = 0.f, csel0 = 0.f, hsel1 = 0.f, csel1 = 0.f;

    const float4* __restrict__ xg4 = (const float4*)g_xg;
    const int jbase = jc * 16;

    #pragma unroll 4
    for (int jj = 0; jj < 16; jj++) {
        const int jn = jbase + jj;
        const float4 x4 = xg4[jn * HID + t];   // (i,f,g,o)
        {
            const float iv = sigm(x4.x + hgi0);
            const float fv = sigm(x4.y + hgf0);
            const float gv = tap (x4.z + hgg0);
            const float ov = sigm(x4.w + hgo0);
            const float cn = fmaf(fv, cp0, iv * gv);
            const float hn = ov * tap(cn);
            hs0 += hn;
            if (jn == sel0) { hsel0 = hn; csel0 = cn; }
        }
        {
            const float iv = sigm(x4.x + hgi1);
            const float fv = sigm(x4.y + hgf1);
            const float gv = tap (x4.z + hgg1);
            const float ov = sigm(x4.w + hgo1);
            const float cn = fmaf(fv, cp1, iv * gv);
            const float hn = ov * tap(cn);
            hs1 += hn;
            if (jn == sel1) { hsel1 = hn; csel1 = cn; }
        }
    }
    g_hsp[jc][(b0+0) * HID + t] = hs0;
    g_hsp[jc][(b0+1) * HID + t] = hs1;
    if ((sel0 >> 4) == jc) { g_h[(b0+0)*HID + t] = hsel0; g_cb[pout][(b0+0)*HID + t] = csel0; }
    if ((sel1 >> 4) == jc) { g_h[(b0+1)*HID + t] = hsel1; g_cb[pout][(b0+1)*HID + t] = csel1; }
}

// ============================================================================
// K_final: cur = (hsel@Wl^T+bl)/(hsum@Wl^T+64bl); out[b] = total[b].cur
// grid 32 x 256 thr: one warp per b; lanes 0..15 num, 16..31 den.
// ============================================================================
__global__ __launch_bounds__(256) void k_final(const float* __restrict__ Wl,
                                               const float* __restrict__ blv,
                                               float* __restrict__ out)
{
    const int w = threadIdx.x >> 5, l = threadIdx.x & 31;
    const int b = blockIdx.x * 8 + w;
    const int r = l & 15;
    const float* __restrict__ wr = Wl + r * HID;
    float acc = 0.f;
    if (l < 16) {
        const float* __restrict__ hx = g_h + b * HID;
        #pragma unroll 8
        for (int k = 0; k < HID; k++) acc = fmaf(wr[k], hx[k], acc);
        acc += blv[r];
    } else {
        const int o = b * HID;
        #pragma unroll 4
        for (int k = 0; k < HID; k++) {
            const float hv = g_hsp[0][o+k] + g_hsp[1][o+k] + g_hsp[2][o+k] + g_hsp[3][o+k];
            acc = fmaf(wr[k], hv, acc);
        }
        acc += 64.0f * blv[r];
    }
    const float den = __shfl_down_sync(0xFFFFFFFFu, acc, 16);
    float v = 0.f;
    if (l < 16) v = g_total[b * RK + l] * acc * frcp(den);
    v += __shfl_xor_sync(0xFFFFFFFFu, v, 8);
    v += __shfl_xor_sync(0xFFFFFFFFu, v, 4);
    v += __shfl_xor_sync(0xFFFFFFFFu, v, 2);
    v += __shfl_xor_sync(0xFFFFFFFFu, v, 1);
    if (l == 0) out[b] = v;
}

// ============================================================================
extern "C" void kernel_launch(void* const* d_in, const int* in_sizes, int n_in,
                              void* d_out, int out_size)
{
    (void)in_sizes; (void)n_in; (void)out_size;
    const int*   x_idx = (const int*)  d_in[0];
    const float* emb   = (const float*)d_in[1];
    const float* Wih   = (const float*)d_in[2];
    const float* Whh   = (const float*)d_in[3];
    const float* bih   = (const float*)d_in[4];
    const float* bhh   = (const float*)d_in[5];
    const float* Wf    = (const float*)d_in[6];
    const float* bf    = (const float*)d_in[7];
    const float* Wm    = (const float*)d_in[8];
    const float* bm    = (const float*)d_in[9];
    const float* Wl    = (const float*)d_in[10];
    const float* bl    = (const float*)d_in[11];
    float* out = (float*)d_out;

    k_initA<<<dim3(2, 16), 256>>>(emb, Wih, bih, bhh);
    k_init2<<<NE, 256>>>();
    k_step0<<<1, 256>>>(Wf, bf, x_idx);
    for (int s = 1; s < NSTEP; s++) {
        k_hgmid<<<dim3(8, 16, 3), 256>>>(Whh, Wm, bm, s >= 2 ? 1 : 0);
        k_cell <<<dim3(BAT / 2, 4), 256>>>(x_idx, s, s & 1, (s + 1) & 1);
    }
    k_final<<<BAT / 8, 256>>>(Wl, bl, out);
}

// round 4
// speedup vs baseline: 2.9687x; 2.6847x over previous
#include <cuda_runtime.h>

#define HID 256
#define G4  1024
#define NE  64
#define BAT 256
#define NSTEP 6
#define RK  16

// ---------------- scratch (allocation-free: device globals) ----------------
__device__ float g_xg[NE * G4];       // gate-interleaved [j][k][4] (float4 per k)
__device__ float g_whhT[HID * G4];    // WhhT[k][m]
__device__ float g_wmT[HID * HID];    // WmT[k][m]
__device__ float g_h0[NE * HID];
__device__ float g_c0[NE * HID];
__device__ float g_sout[NE * RK];     // step0 logits (pre-normalize)

// ---------------- transcendentals: single-MUFU tanh.approx -----------------
__device__ __forceinline__ float tap(float x){ float y; asm("tanh.approx.f32 %0,%1;" : "=f"(y) : "f"(x)); return y; }
__device__ __forceinline__ float frcp(float x){ float y; asm("rcp.approx.f32 %0,%1;" : "=f"(y) : "f"(x)); return y; }
__device__ __forceinline__ float sigm(float x){ return fmaf(0.5f, tap(0.5f * x), 0.5f); }

// ============================================================================
// K_prep: blocks 0..31  -> xg GEMM (gate-interleaved, +bih+bhh)
//         blocks 32..287 -> WhhT transpose (1024x256 -> 256x1024), 32x32 tiles
//         blocks 288..351-> WmT transpose (256x256), 32x32 tiles
// ============================================================================
__global__ __launch_bounds__(256) void k_prep(const float* __restrict__ emb,
                                              const float* __restrict__ Wih,
                                              const float* __restrict__ bih,
                                              const float* __restrict__ bhh,
                                              const float* __restrict__ Whh,
                                              const float* __restrict__ Wm)
{
    const int id = blockIdx.x, t = threadIdx.x;
    if (id < 32) {
        __shared__ float As[16][34];
        __shared__ float Bs[16][68];
        const int tx = t & 15, ty = t >> 4;
        const int b0 = (id & 1) * 32;
        const int m0 = (id >> 1) * 64;
        float acc[2][4] = {};
        for (int k0 = 0; k0 < HID; k0 += 16) {
            if (t < 128) {
                const int r = t >> 2, c = (t & 3) * 4;
                const float4 v = *(const float4*)&emb[(b0 + r) * HID + k0 + c];
                As[c+0][r] = v.x; As[c+1][r] = v.y; As[c+2][r] = v.z; As[c+3][r] = v.w;
            }
            {
                const int r = t >> 2, c = (t & 3) * 4;
                const float4 v = *(const float4*)&Wih[(m0 + r) * HID + k0 + c];
                Bs[c+0][r] = v.x; Bs[c+1][r] = v.y; Bs[c+2][r] = v.z; Bs[c+3][r] = v.w;
            }
            __syncthreads();
            #pragma unroll
            for (int kk = 0; kk < 16; kk++) {
                const float2 a = *(const float2*)&As[kk][2 * ty];
                const float4 bv = *(const float4*)&Bs[kk][4 * tx];
                acc[0][0] = fmaf(a.x, bv.x, acc[0][0]); acc[0][1] = fmaf(a.x, bv.y, acc[0][1]);
                acc[0][2] = fmaf(a.x, bv.z, acc[0][2]); acc[0][3] = fmaf(a.x, bv.w, acc[0][3]);
                acc[1][0] = fmaf(a.y, bv.x, acc[1][0]); acc[1][1] = fmaf(a.y, bv.y, acc[1][1]);
                acc[1][2] = fmaf(a.y, bv.z, acc[1][2]); acc[1][3] = fmaf(a.y, bv.w, acc[1][3]);
            }
            __syncthreads();
        }
        const int mc0 = m0 + 4 * tx;
        const int gate = mc0 >> 8;
        const int kc0  = mc0 & 255;
        float bias[4];
        #pragma unroll
        for (int jj = 0; jj < 4; jj++) bias[jj] = bih[mc0 + jj] + bhh[mc0 + jj];
        #pragma unroll
        for (int i = 0; i < 2; i++) {
            const int jr = b0 + 2 * ty + i;
            #pragma unroll
            for (int jj = 0; jj < 4; jj++)
                g_xg[jr * G4 + 4 * (kc0 + jj) + gate] = acc[i][jj] + bias[jj];
        }
    } else if (id < 288) {
        __shared__ float T[32][33];
        const int tid = id - 32;
        const int mi = tid & 31, ki = tid >> 5;   // 32 m-tiles x 8 k-tiles
        const int r = t >> 3, c4 = (t & 7) * 4;
        const float4 v = *(const float4*)&Whh[(mi * 32 + r) * HID + ki * 32 + c4];
        T[r][c4+0] = v.x; T[r][c4+1] = v.y; T[r][c4+2] = v.z; T[r][c4+3] = v.w;
        __syncthreads();
        const int mm = t & 31, kk0 = t >> 5;
        #pragma unroll
        for (int i = 0; i < 4; i++) {
            const int kk = kk0 + 8 * i;
            g_whhT[(ki * 32 + kk) * G4 + mi * 32 + mm] = T[mm][kk];
        }
    } else {
        __shared__ float T2[32][33];
        const int tid = id - 288;
        const int mi = tid & 7, ki = tid >> 3;    // 8 x 8 tiles
        const int r = t >> 3, c4 = (t & 7) * 4;
        const float4 v = *(const float4*)&Wm[(mi * 32 + r) * HID + ki * 32 + c4];
        T2[r][c4+0] = v.x; T2[r][c4+1] = v.y; T2[r][c4+2] = v.z; T2[r][c4+3] = v.w;
        __syncthreads();
        const int mm = t & 31, kk0 = t >> 5;
        #pragma unroll
        for (int i = 0; i < 4; i++) {
            const int kk = kk0 + 8 * i;
            g_wmT[(ki * 32 + kk) * HID + mi * 32 + mm] = T2[mm][kk];
        }
    }
}

// ============================================================================
// K_h0: grid 64 (one j per block): h0/c0 = cell(xg, c=0), sout = h0@Wf^T + bf
// ============================================================================
__global__ __launch_bounds__(256) void k_h0(const float* __restrict__ Wf,
                                            const float* __restrict__ bf)
{
    __shared__ float sh0[HID];
    const int j = blockIdx.x, t = threadIdx.x;
    const float4 x4 = ((const float4*)g_xg)[j * HID + t];   // (i,f,g,o)
    const float c0 = sigm(x4.x) * tap(x4.z);
    const float h0 = sigm(x4.w) * tap(c0);
    g_c0[j * HID + t] = c0;
    g_h0[j * HID + t] = h0;
    sh0[t] = h0;
    __syncthreads();
    const int w = t >> 5, l = t & 31;
    #pragma unroll
    for (int rr = 0; rr < 2; rr++) {
        const int r = w + 8 * rr;
        float a = 0.f;
        #pragma unroll
        for (int q = 0; q < 8; q++) {
            const int k = l + 32 * q;
            a = fmaf(sh0[k], Wf[r * HID + k], a);
        }
        a += __shfl_xor_sync(0xFFFFFFFFu, a, 16);
        a += __shfl_xor_sync(0xFFFFFFFFu, a, 8);
        a += __shfl_xor_sync(0xFFFFFFFFu, a, 4);
        a += __shfl_xor_sync(0xFFFFFFFFu, a, 2);
        a += __shfl_xor_sync(0xFFFFFFFFu, a, 1);
        if (l == 0) g_sout[j * RK + r] = a + bf[r];
    }
}

// ============================================================================
// K_chain: grid 128 blocks x 512 thr. Block owns batches b0, b0+1 and runs the
// whole 5-step recurrence in smem. half = t>>8 splits K (GEMV/mid) or J (cell).
// ============================================================================
__global__ __launch_bounds__(512) void k_chain(const int* __restrict__ xidx,
                                               const float* __restrict__ bm,
                                               const float* __restrict__ Wl,
                                               const float* __restrict__ bl,
                                               float* __restrict__ out)
{
    __shared__ float sh_h[2][HID];            // current h (2 batches)
    __shared__ float sh_c[2][HID];            // current c
    __shared__ float sh_hgp[2][2][G4];        // [half][b][m] GEMV partials; [0] = combined hg
    __shared__ float s_cur[2][HID];
    __shared__ float st_tot[2][RK];
    __shared__ float s_rcl[RK];

    const int t = threadIdx.x;
    const int half = t >> 8, tt = t & 255;
    const int b0 = blockIdx.x * 2;
    const float4* __restrict__ xg4 = (const float4*)g_xg;
    float* s_hs = &sh_hgp[1][0][0];           // [2 half][2 b][256] partial hsum; combined -> [b][256]
    float* s_md = &sh_hgp[0][0][0];           // mid partials [half][4][256] (hg dead by then)

    // ---- Phase A: step-0 normalize + gather ----
    if (t < RK) {
        float s = 0.f;
        #pragma unroll 8
        for (int j = 0; j < NE; j++) s += g_sout[j * RK + t];
        s_rcl[t] = 1.0f / s;
    }
    {
        const int sel = xidx[(b0 + half) * NSTEP + 0];
        sh_h[half][tt] = g_h0[sel * HID + tt];
        sh_c[half][tt] = g_c0[sel * HID + tt];
    }
    __syncthreads();
    if (t < 2 * RK) {
        const int b = t >> 4, r = t & 15;
        const int sel = xidx[(b0 + b) * NSTEP + 0];
        st_tot[b][r] = g_sout[sel * RK + r] * s_rcl[r];
    }

    for (int s = 1; s < NSTEP; s++) {
        __syncthreads();
        // ---- GEMV: hg[b][m] = sum_k h[b][k] * WhhT[k][m], k-split by half ----
        {
            const int kb = half * 128;
            const int mb = tt * 4;
            float4 ac0 = {0,0,0,0}, ac1 = {0,0,0,0};
            for (int k4 = 0; k4 < 128; k4 += 4) {
                const float* wrow = g_whhT + (kb + k4) * G4 + mb;
                const float4 w0 = *(const float4*)(wrow);
                const float4 w1 = *(const float4*)(wrow + G4);
                const float4 w2 = *(const float4*)(wrow + 2 * G4);
                const float4 w3 = *(const float4*)(wrow + 3 * G4);
                const float4 h0v = *(const float4*)&sh_h[0][kb + k4];
                const float4 h1v = *(const float4*)&sh_h[1][kb + k4];
                ac0.x = fmaf(h0v.x, w0.x, fmaf(h0v.y, w1.x, fmaf(h0v.z, w2.x, fmaf(h0v.w, w3.x, ac0.x))));
                ac0.y = fmaf(h0v.x, w0.y, fmaf(h0v.y, w1.y, fmaf(h0v.z, w2.y, fmaf(h0v.w, w3.y, ac0.y))));
                ac0.z = fmaf(h0v.x, w0.z, fmaf(h0v.y, w1.z, fmaf(h0v.z, w2.z, fmaf(h0v.w, w3.z, ac0.z))));
                ac0.w = fmaf(h0v.x, w0.w, fmaf(h0v.y, w1.w, fmaf(h0v.z, w2.w, fmaf(h0v.w, w3.w, ac0.w))));
                ac1.x = fmaf(h1v.x, w0.x, fmaf(h1v.y, w1.x, fmaf(h1v.z, w2.x, fmaf(h1v.w, w3.x, ac1.x))));
                ac1.y = fmaf(h1v.x, w0.y, fmaf(h1v.y, w1.y, fmaf(h1v.z, w2.y, fmaf(h1v.w, w3.y, ac1.y))));
                ac1.z = fmaf(h1v.x, w0.z, fmaf(h1v.y, w1.z, fmaf(h1v.z, w2.z, fmaf(h1v.w, w3.z, ac1.z))));
                ac1.w = fmaf(h1v.x, w0.w, fmaf(h1v.y, w1.w, fmaf(h1v.z, w2.w, fmaf(h1v.w, w3.w, ac1.w))));
            }
            *(float4*)&sh_hgp[half][0][mb] = ac0;
            *(float4*)&sh_hgp[half][1][mb] = ac1;
        }
        __syncthreads();
        {   // combine k-halves: 2048 values, 4 per thread
            const int lin = t * 4;
            float4 a = *(const float4*)(&sh_hgp[0][0][0] + lin);
            const float4 b = *(const float4*)(&sh_hgp[1][0][0] + lin);
            a.x += b.x; a.y += b.y; a.z += b.z; a.w += b.w;
            *(float4*)(&sh_hgp[0][0][0] + lin) = a;
        }
        __syncthreads();
        // ---- CELL: j-split by half (32 j each), k = tt ----
        const int selb0 = xidx[b0 * NSTEP + s];
        const int selb1 = xidx[(b0 + 1) * NSTEP + s];
        const int k = tt;
        const float hgI0 = sh_hgp[0][0][k],         hgF0 = sh_hgp[0][0][HID + k];
        const float hgG0 = sh_hgp[0][0][2*HID + k], hgO0 = sh_hgp[0][0][3*HID + k];
        const float hgI1 = sh_hgp[0][1][k],         hgF1 = sh_hgp[0][1][HID + k];
        const float hgG1 = sh_hgp[0][1][2*HID + k], hgO1 = sh_hgp[0][1][3*HID + k];
        const float cp0 = sh_c[0][k], cp1 = sh_c[1][k];
        __syncthreads();   // all reads of sh_c / gates done before owners overwrite
        float hs0 = 0.f, hs1 = 0.f, hv0 = 0.f, cv0 = 0.f, hv1 = 0.f, cv1 = 0.f;
        const int jb = half * 32;
        #pragma unroll 4
        for (int j = jb; j < jb + 32; j++) {
            const float4 x4 = xg4[j * HID + k];
            {
                const float iv = sigm(x4.x + hgI0);
                const float fv = sigm(x4.y + hgF0);
                const float gv = tap (x4.z + hgG0);
                const float ov = sigm(x4.w + hgO0);
                const float cn = fmaf(fv, cp0, iv * gv);
                const float hn = ov * tap(cn);
                hs0 += hn;
                if (j == selb0) { hv0 = hn; cv0 = cn; }
            }
            {
                const float iv = sigm(x4.x + hgI1);
                const float fv = sigm(x4.y + hgF1);
                const float gv = tap (x4.z + hgG1);
                const float ov = sigm(x4.w + hgO1);
                const float cn = fmaf(fv, cp1, iv * gv);
                const float hn = ov * tap(cn);
                hs1 += hn;
                if (j == selb1) { hv1 = hn; cv1 = cn; }
            }
        }
        s_hs[(half * 2 + 0) * HID + k] = hs0;
        s_hs[(half * 2 + 1) * HID + k] = hs1;
        if ((selb0 >> 5) == half) { sh_h[0][k] = hv0; sh_c[0][k] = cv0; }
        if ((selb1 >> 5) == half) { sh_h[1][k] = hv1; sh_c[1][k] = cv1; }
        __syncthreads();
        {   // combine hsum halves -> s_hs[b*256 + k2]
            const int b = t >> 8, k2 = t & 255;
            s_hs[b * HID + k2] += s_hs[(2 + b) * HID + k2];
        }
        __syncthreads();

        if (s < NSTEP - 1) {
            // ---- MID: num/den GEMV vs WmT (k-split by half), then total @= cur ----
            const int kb = half * 128;
            const int m = tt;
            float n0 = 0.f, n1 = 0.f, d0 = 0.f, d1 = 0.f;
            for (int k4 = 0; k4 < 128; k4 += 4) {
                const float4 h0v = *(const float4*)&sh_h[0][kb + k4];
                const float4 h1v = *(const float4*)&sh_h[1][kb + k4];
                const float4 u0v = *(const float4*)&s_hs[0 * HID + kb + k4];
                const float4 u1v = *(const float4*)&s_hs[1 * HID + kb + k4];
                const float w0 = g_wmT[(kb + k4 + 0) * HID + m];
                const float w1 = g_wmT[(kb + k4 + 1) * HID + m];
                const float w2 = g_wmT[(kb + k4 + 2) * HID + m];
                const float w3 = g_wmT[(kb + k4 + 3) * HID + m];
                n0 = fmaf(w0, h0v.x, fmaf(w1, h0v.y, fmaf(w2, h0v.z, fmaf(w3, h0v.w, n0))));
                n1 = fmaf(w0, h1v.x, fmaf(w1, h1v.y, fmaf(w2, h1v.z, fmaf(w3, h1v.w, n1))));
                d0 = fmaf(w0, u0v.x, fmaf(w1, u0v.y, fmaf(w2, u0v.z, fmaf(w3, u0v.w, d0))));
                d1 = fmaf(w0, u1v.x, fmaf(w1, u1v.y, fmaf(w2, u1v.z, fmaf(w3, u1v.w, d1))));
            }
            s_md[(half * 4 + 0) * HID + m] = n0;
            s_md[(half * 4 + 1) * HID + m] = n1;
            s_md[(half * 4 + 2) * HID + m] = d0;
            s_md[(half * 4 + 3) * HID + m] = d1;
            __syncthreads();
            if (half == 0) {
                const float n0f = s_md[0 * HID + tt] + s_md[4 * HID + tt];
                const float n1f = s_md[1 * HID + tt] + s_md[5 * HID + tt];
                const float d0f = s_md[2 * HID + tt] + s_md[6 * HID + tt];
                const float d1f = s_md[3 * HID + tt] + s_md[7 * HID + tt];
                const float bmv = bm[tt];
                s_cur[0][tt] = (n0f + bmv) * frcp(d0f + 64.0f * bmv);
                s_cur[1][tt] = (n1f + bmv) * frcp(d1f + 64.0f * bmv);
            }
            __syncthreads();
            float ntot = 0.f;
            const int ub = t >> 4, ur = t & 15;
            if (t < 32) {
                #pragma unroll
                for (int r1 = 0; r1 < RK; r1++)
                    ntot = fmaf(st_tot[ub][r1], s_cur[ub][r1 * RK + ur], ntot);
            }
            __syncthreads();
            if (t < 32) st_tot[ub][ur] = ntot;
        } else {
            // ---- FINAL: cur = (hsel.Wl+bl)/(hsum.Wl+64bl); out = total . cur ----
            if (t < 64) {
                const int b = t >> 5, l = t & 31;
                const int r = l & 15, role = l >> 4;
                const float* __restrict__ src = role ? (s_hs + b * HID) : &sh_h[b][0];
                float acc = 0.f;
                #pragma unroll 8
                for (int kk = 0; kk < HID; kk++)
                    acc = fmaf(Wl[r * HID + kk], src[kk], acc);
                acc += (role ? 64.0f : 1.0f) * bl[r];
                const float den = __shfl_down_sync(0xFFFFFFFFu, acc, 16);
                float v = 0.f;
                if (!role) v = st_tot[b][r] * acc * frcp(den);
                v += __shfl_xor_sync(0xFFFFFFFFu, v, 8);
                v += __shfl_xor_sync(0xFFFFFFFFu, v, 4);
                v += __shfl_xor_sync(0xFFFFFFFFu, v, 2);
                v += __shfl_xor_sync(0xFFFFFFFFu, v, 1);
                if (l == 0) out[b0 + b] = v;
            }
        }
    }
}

// ============================================================================
extern "C" void kernel_launch(void* const* d_in, const int* in_sizes, int n_in,
                              void* d_out, int out_size)
{
    (void)in_sizes; (void)n_in; (void)out_size;
    const int*   x_idx = (const int*)  d_in[0];
    const float* emb   = (const float*)d_in[1];
    const float* Wih   = (const float*)d_in[2];
    const float* Whh   = (const float*)d_in[3];
    const float* bih   = (const float*)d_in[4];
    const float* bhh   = (const float*)d_in[5];
    const float* Wf    = (const float*)d_in[6];
    const float* bf    = (const float*)d_in[7];
    const float* Wm    = (const float*)d_in[8];
    const float* bm    = (const float*)d_in[9];
    const float* Wl    = (const float*)d_in[10];
    const float* bl    = (const float*)d_in[11];
    float* out = (float*)d_out;

    k_prep <<<352, 256>>>(emb, Wih, bih, bhh, Whh, Wm);
    k_h0   <<<NE, 256>>>(Wf, bf);
    k_chain<<<BAT / 2, 512>>>(x_idx, bm, Wl, bl, out);
}

// round 7
// speedup vs baseline: 3.0875x; 1.0400x over previous
#include <cuda_runtime.h>
#include <cuda_fp16.h>

#define HID 256
#define G4  1024
#define NE  64
#define BAT 256
#define NSTEP 6
#define RK  16

// ---------------- scratch (allocation-free: device globals) ----------------
__device__ __align__(16) float   g_xg[NE * G4];      // fp32 gate-interleaved [j][k][4]
__device__ __align__(16) uint2   g_xgh[NE * HID];    // fp16 (i,f)(g,o) packed, 8B per (j,k)
__device__ __align__(16) __half2 g_whh2[128 * G4];   // PW[kp][m] = (WhhT[2kp][m], WhhT[2kp+1][m])
__device__ __align__(16) __half2 g_wm2[128 * HID];   // PM[kp][m]
__device__ __align__(16) float   g_h0[NE * HID];
__device__ __align__(16) float   g_c0[NE * HID];
__device__ __align__(16) float   g_sout[NE * RK];

// ---------------- transcendentals: single-MUFU tanh.approx -----------------
__device__ __forceinline__ float tap(float x){ float y; asm("tanh.approx.f32 %0,%1;" : "=f"(y) : "f"(x)); return y; }
__device__ __forceinline__ float frcp(float x){ float y; asm("rcp.approx.f32 %0,%1;" : "=f"(y) : "f"(x)); return y; }
__device__ __forceinline__ float sigm(float x){ return fmaf(0.5f, tap(0.5f * x), 0.5f); }
__device__ __forceinline__ float2 h2f(__half2 h){ return __half22float2(h); }

// ============================================================================
// K_prep: blocks 0..31  -> xg GEMM (fp32, gate-interleaved, +bih+bhh)
//         blocks 32..95 -> Whh -> g_whh2  (64x64 tiles, fp16 k-pair pack)
//         blocks 96..111-> Wm  -> g_wm2   (64x64 tiles)
// Transpose tile T[64][65]: float4 GMEM loads (MLP=4) + SCALAR smem stores —
// row stride 260B is not 16B-aligned, so STS.128 into T would trap (round-5/6
// 'misaligned address' root cause).
// ============================================================================
__global__ __launch_bounds__(256) void k_prep(const float* __restrict__ emb,
                                              const float* __restrict__ Wih,
                                              const float* __restrict__ bih,
                                              const float* __restrict__ bhh,
                                              const float* __restrict__ Whh,
                                              const float* __restrict__ Wm)
{
    const int id = blockIdx.x, t = threadIdx.x;
    if (id < 32) {
        __shared__ __align__(16) float As[16][34];
        __shared__ __align__(16) float Bs[16][68];
        const int tx = t & 15, ty = t >> 4;
        const int b0 = (id & 1) * 32;
        const int m0 = (id >> 1) * 64;
        float acc[2][4] = {};
        for (int k0 = 0; k0 < HID; k0 += 16) {
            if (t < 128) {
                const int r = t >> 2, c = (t & 3) * 4;
                const float4 v = *(const float4*)&emb[(b0 + r) * HID + k0 + c];
                As[c+0][r] = v.x; As[c+1][r] = v.y; As[c+2][r] = v.z; As[c+3][r] = v.w;
            }
            {
                const int r = t >> 2, c = (t & 3) * 4;
                const float4 v = *(const float4*)&Wih[(m0 + r) * HID + k0 + c];
                Bs[c+0][r] = v.x; Bs[c+1][r] = v.y; Bs[c+2][r] = v.z; Bs[c+3][r] = v.w;
            }
            __syncthreads();
            #pragma unroll
            for (int kk = 0; kk < 16; kk++) {
                const float2 a = *(const float2*)&As[kk][2 * ty];
                const float4 bv = *(const float4*)&Bs[kk][4 * tx];
                acc[0][0] = fmaf(a.x, bv.x, acc[0][0]); acc[0][1] = fmaf(a.x, bv.y, acc[0][1]);
                acc[0][2] = fmaf(a.x, bv.z, acc[0][2]); acc[0][3] = fmaf(a.x, bv.w, acc[0][3]);
                acc[1][0] = fmaf(a.y, bv.x, acc[1][0]); acc[1][1] = fmaf(a.y, bv.y, acc[1][1]);
                acc[1][2] = fmaf(a.y, bv.z, acc[1][2]); acc[1][3] = fmaf(a.y, bv.w, acc[1][3]);
            }
            __syncthreads();
        }
        const int mc0 = m0 + 4 * tx;
        const int gate = mc0 >> 8;
        const int kc0  = mc0 & 255;
        float bias[4];
        #pragma unroll
        for (int jj = 0; jj < 4; jj++) bias[jj] = bih[mc0 + jj] + bhh[mc0 + jj];
        #pragma unroll
        for (int i = 0; i < 2; i++) {
            const int jr = b0 + 2 * ty + i;
            #pragma unroll
            for (int jj = 0; jj < 4; jj++)
                g_xg[jr * G4 + 4 * (kc0 + jj) + gate] = acc[i][jj] + bias[jj];
        }
    } else {
        __shared__ float T[64][65];
        const bool isWhh = (id < 96);
        const int tid = isWhh ? (id - 32) : (id - 96);
        const int mi  = isWhh ? (tid & 15) : (tid & 3);   // 64-row m-tile index
        const int ki  = isWhh ? (tid >> 4) : (tid >> 2);  // 64-col k-tile index
        const float* __restrict__ src = isWhh ? Whh : Wm;
        {
            const int c4 = (t & 15) * 4;       // k offset within tile (16B-aligned in GMEM)
            const int r0 = t >> 4;             // 0..15
            const float4 v0 = *(const float4*)&src[(mi * 64 + r0 +  0) * HID + ki * 64 + c4];
            const float4 v1 = *(const float4*)&src[(mi * 64 + r0 + 16) * HID + ki * 64 + c4];
            const float4 v2 = *(const float4*)&src[(mi * 64 + r0 + 32) * HID + ki * 64 + c4];
            const float4 v3 = *(const float4*)&src[(mi * 64 + r0 + 48) * HID + ki * 64 + c4];
            // scalar stores: T row stride (65 floats = 260B) is NOT float4-aligned
            T[r0 +  0][c4+0] = v0.x; T[r0 +  0][c4+1] = v0.y; T[r0 +  0][c4+2] = v0.z; T[r0 +  0][c4+3] = v0.w;
            T[r0 + 16][c4+0] = v1.x; T[r0 + 16][c4+1] = v1.y; T[r0 + 16][c4+2] = v1.z; T[r0 + 16][c4+3] = v1.w;
            T[r0 + 32][c4+0] = v2.x; T[r0 + 32][c4+1] = v2.y; T[r0 + 32][c4+2] = v2.z; T[r0 + 32][c4+3] = v2.w;
            T[r0 + 48][c4+0] = v3.x; T[r0 + 48][c4+1] = v3.y; T[r0 + 48][c4+2] = v3.z; T[r0 + 48][c4+3] = v3.w;
        }
        __syncthreads();
        const int m_l = t & 63, kp0 = t >> 6;  // kp0 0..3
        const int rowlen = isWhh ? G4 : HID;
        __half2* __restrict__ dst = isWhh ? g_whh2 : g_wm2;
        #pragma unroll
        for (int i = 0; i < 8; i++) {
            const int kpl = kp0 + 4 * i;       // 0..31
            const __half2 h2 = __floats2half2_rn(T[m_l][2 * kpl], T[m_l][2 * kpl + 1]);
            dst[(ki * 32 + kpl) * rowlen + mi * 64 + m_l] = h2;
        }
    }
}

// ============================================================================
// K_h0: grid 64: h0/c0 = cell(xg, c=0); sout = h0@Wf^T + bf; emit fp16 xg.
// ============================================================================
__global__ __launch_bounds__(256) void k_h0(const float* __restrict__ Wf,
                                            const float* __restrict__ bf)
{
    __shared__ float sh0[HID];
    const int j = blockIdx.x, t = threadIdx.x;
    const float4 x4 = ((const float4*)g_xg)[j * HID + t];   // (i,f,g,o)
    {
        union { __half2 h2[2]; uint2 u; } p;
        p.h2[0] = __floats2half2_rn(x4.x, x4.y);
        p.h2[1] = __floats2half2_rn(x4.z, x4.w);
        g_xgh[j * HID + t] = p.u;
    }
    const float c0 = sigm(x4.x) * tap(x4.z);
    const float h0 = sigm(x4.w) * tap(c0);
    g_c0[j * HID + t] = c0;
    g_h0[j * HID + t] = h0;
    sh0[t] = h0;
    __syncthreads();
    const int w = t >> 5, l = t & 31;
    #pragma unroll
    for (int rr = 0; rr < 2; rr++) {
        const int r = w + 8 * rr;
        float a = 0.f;
        #pragma unroll
        for (int q = 0; q < 8; q++) {
            const int k = l + 32 * q;
            a = fmaf(sh0[k], Wf[r * HID + k], a);
        }
        a += __shfl_xor_sync(0xFFFFFFFFu, a, 16);
        a += __shfl_xor_sync(0xFFFFFFFFu, a, 8);
        a += __shfl_xor_sync(0xFFFFFFFFu, a, 4);
        a += __shfl_xor_sync(0xFFFFFFFFu, a, 2);
        a += __shfl_xor_sync(0xFFFFFFFFu, a, 1);
        if (l == 0) g_sout[j * RK + r] = a + bf[r];
    }
}

// ============================================================================
// K_chain: 128 blocks x 512 thr. Block owns batches b0,b0+1; full recurrence
// in smem. half = t>>8 splits K (GEMV/mid) or J (cell). fp16 weight streams.
// ============================================================================
__global__ __launch_bounds__(512) void k_chain(const int* __restrict__ xidx,
                                               const float* __restrict__ bm,
                                               const float* __restrict__ Wl,
                                               const float* __restrict__ bl,
                                               float* __restrict__ out)
{
    __shared__ __align__(16) float sh_h[2][HID];
    __shared__ __align__(16) float sh_c[2][HID];
    __shared__ __align__(16) float sh_hgp[2][2][G4];   // GEMV partials; [0] = combined hg
    __shared__ __align__(16) float s_cur[2][HID];
    __shared__ float st_tot[2][RK];
    __shared__ float s_rcl[RK];

    const int t = threadIdx.x;
    const int half = t >> 8, tt = t & 255;
    const int b0 = blockIdx.x * 2;
    float* s_hs = &sh_hgp[1][0][0];         // hsum partials / combined
    float* s_md = &sh_hgp[0][0][0];         // mid partials (hg dead)

    // ---- Phase A: step-0 normalize + gather ----
    if (t < RK) {
        float s = 0.f;
        #pragma unroll 8
        for (int j = 0; j < NE; j++) s += g_sout[j * RK + t];
        s_rcl[t] = 1.0f / s;
    }
    {
        const int sel = xidx[(b0 + half) * NSTEP + 0];
        sh_h[half][tt] = g_h0[sel * HID + tt];
        sh_c[half][tt] = g_c0[sel * HID + tt];
    }
    __syncthreads();
    if (t < 2 * RK) {
        const int b = t >> 4, r = t & 15;
        const int sel = xidx[(b0 + b) * NSTEP + 0];
        st_tot[b][r] = g_sout[sel * RK + r] * s_rcl[r];
    }

    for (int s = 1; s < NSTEP; s++) {
        __syncthreads();
        // ---- GEMV: hg[b][m] = sum_k h[b][k]*WhhT[k][m]; kp-split by half ----
        {
            const int kpb = half * 64;             // 64 kp = 128 k per half
            const int mb  = tt * 4;
            float4 ac0 = {0,0,0,0}, ac1 = {0,0,0,0};
            #pragma unroll 4
            for (int kp = 0; kp < 64; kp++) {
                const uint4 w = *(const uint4*)&g_whh2[(kpb + kp) * G4 + mb];
                const float2 hA = *(const float2*)&sh_h[0][2 * (kpb + kp)];
                const float2 hB = *(const float2*)&sh_h[1][2 * (kpb + kp)];
                const float2 p0 = h2f(*(const __half2*)&w.x);
                const float2 p1 = h2f(*(const __half2*)&w.y);
                const float2 p2 = h2f(*(const __half2*)&w.z);
                const float2 p3 = h2f(*(const __half2*)&w.w);
                ac0.x = fmaf(hA.x, p0.x, fmaf(hA.y, p0.y, ac0.x));
                ac0.y = fmaf(hA.x, p1.x, fmaf(hA.y, p1.y, ac0.y));
                ac0.z = fmaf(hA.x, p2.x, fmaf(hA.y, p2.y, ac0.z));
                ac0.w = fmaf(hA.x, p3.x, fmaf(hA.y, p3.y, ac0.w));
                ac1.x = fmaf(hB.x, p0.x, fmaf(hB.y, p0.y, ac1.x));
                ac1.y = fmaf(hB.x, p1.x, fmaf(hB.y, p1.y, ac1.y));
                ac1.z = fmaf(hB.x, p2.x, fmaf(hB.y, p2.y, ac1.z));
                ac1.w = fmaf(hB.x, p3.x, fmaf(hB.y, p3.y, ac1.w));
            }
            *(float4*)&sh_hgp[half][0][mb] = ac0;
            *(float4*)&sh_hgp[half][1][mb] = ac1;
        }
        __syncthreads();
        {   // combine k-halves: 2048 floats, 4 per thread
            const int lin = t * 4;
            float4 a = *(const float4*)(&sh_hgp[0][0][0] + lin);
            const float4 b = *(const float4*)(&sh_hgp[1][0][0] + lin);
            a.x += b.x; a.y += b.y; a.z += b.z; a.w += b.w;
            *(float4*)(&sh_hgp[0][0][0] + lin) = a;
        }
        __syncthreads();
        // ---- CELL: j-split by half (32 j each), k = tt ----
        const int selb0 = xidx[b0 * NSTEP + s];
        const int selb1 = xidx[(b0 + 1) * NSTEP + s];
        const int k = tt;
        const float hgI0 = sh_hgp[0][0][k],         hgF0 = sh_hgp[0][0][HID + k];
        const float hgG0 = sh_hgp[0][0][2*HID + k], hgO0 = sh_hgp[0][0][3*HID + k];
        const float hgI1 = sh_hgp[0][1][k],         hgF1 = sh_hgp[0][1][HID + k];
        const float hgG1 = sh_hgp[0][1][2*HID + k], hgO1 = sh_hgp[0][1][3*HID + k];
        const float cp0 = sh_c[0][k], cp1 = sh_c[1][k];
        __syncthreads();   // reads of sh_c / gates done before owners overwrite
        float hs0 = 0.f, hs1 = 0.f, hv0 = 0.f, cv0 = 0.f, hv1 = 0.f, cv1 = 0.f;
        const int jb = half * 32;
        #pragma unroll 4
        for (int j = jb; j < jb + 32; j++) {
            const uint2 u = g_xgh[j * HID + k];
            const float2 vif = h2f(*(const __half2*)&u.x);   // (i,f)
            const float2 vgo = h2f(*(const __half2*)&u.y);   // (g,o)
            {
                const float iv = sigm(vif.x + hgI0);
                const float fv = sigm(vif.y + hgF0);
                const float gv = tap (vgo.x + hgG0);
                const float ov = sigm(vgo.y + hgO0);
                const float cn = fmaf(fv, cp0, iv * gv);
                const float hn = ov * tap(cn);
                hs0 += hn;
                if (j == selb0) { hv0 = hn; cv0 = cn; }
            }
            {
                const float iv = sigm(vif.x + hgI1);
                const float fv = sigm(vif.y + hgF1);
                const float gv = tap (vgo.x + hgG1);
                const float ov = sigm(vgo.y + hgO1);
                const float cn = fmaf(fv, cp1, iv * gv);
                const float hn = ov * tap(cn);
                hs1 += hn;
                if (j == selb1) { hv1 = hn; cv1 = cn; }
            }
        }
        s_hs[(half * 2 + 0) * HID + k] = hs0;
        s_hs[(half * 2 + 1) * HID + k] = hs1;
        if ((selb0 >> 5) == half) { sh_h[0][k] = hv0; sh_c[0][k] = cv0; }
        if ((selb1 >> 5) == half) { sh_h[1][k] = hv1; sh_c[1][k] = cv1; }
        __syncthreads();
        {   // combine hsum halves
            const int b = t >> 8, k2 = t & 255;
            s_hs[b * HID + k2] += s_hs[(2 + b) * HID + k2];
        }
        __syncthreads();

        if (s < NSTEP - 1) {
            // ---- MID: num/den GEMV vs WmT (kp-split), total @= cur ----
            const int kpb = half * 64;
            const int m = tt;
            float n0 = 0.f, n1 = 0.f, d0 = 0.f, d1 = 0.f;
            #pragma unroll 4
            for (int kp = 0; kp < 64; kp++) {
                const float2 w = h2f(g_wm2[(kpb + kp) * HID + m]);
                const float2 hA = *(const float2*)&sh_h[0][2 * (kpb + kp)];
                const float2 hB = *(const float2*)&sh_h[1][2 * (kpb + kp)];
                const float2 uA = *(const float2*)&s_hs[0 * HID + 2 * (kpb + kp)];
                const float2 uB = *(const float2*)&s_hs[1 * HID + 2 * (kpb + kp)];
                n0 = fmaf(w.x, hA.x, fmaf(w.y, hA.y, n0));
                n1 = fmaf(w.x, hB.x, fmaf(w.y, hB.y, n1));
                d0 = fmaf(w.x, uA.x, fmaf(w.y, uA.y, d0));
                d1 = fmaf(w.x, uB.x, fmaf(w.y, uB.y, d1));
            }
            s_md[(half * 4 + 0) * HID + m] = n0;
            s_md[(half * 4 + 1) * HID + m] = n1;
            s_md[(half * 4 + 2) * HID + m] = d0;
            s_md[(half * 4 + 3) * HID + m] = d1;
            __syncthreads();
            if (half == 0) {
                const float n0f = s_md[0 * HID + tt] + s_md[4 * HID + tt];
                const float n1f = s_md[1 * HID + tt] + s_md[5 * HID + tt];
                const float d0f = s_md[2 * HID + tt] + s_md[6 * HID + tt];
                const float d1f = s_md[3 * HID + tt] + s_md[7 * HID + tt];
                const float bmv = bm[tt];
                s_cur[0][tt] = (n0f + bmv) * frcp(d0f + 64.0f * bmv);
                s_cur[1][tt] = (n1f + bmv) * frcp(d1f + 64.0f * bmv);
            }
            __syncthreads();
            float ntot = 0.f;
            const int ub = t >> 4, ur = t & 15;
            if (t < 32) {
                #pragma unroll
                for (int r1 = 0; r1 < RK; r1++)
                    ntot = fmaf(st_tot[ub][r1], s_cur[ub][r1 * RK + ur], ntot);
            }
            __syncthreads();
            if (t < 32) st_tot[ub][ur] = ntot;
        } else {
            // ---- FINAL ----
            if (t < 64) {
                const int b = t >> 5, l = t & 31;
                const int r = l & 15, role = l >> 4;
                const float* __restrict__ src = role ? (s_hs + b * HID) : &sh_h[b][0];
                float acc = 0.f;
                #pragma unroll 8
                for (int kk = 0; kk < HID; kk++)
                    acc = fmaf(Wl[r * HID + kk], src[kk], acc);
                acc += (role ? 64.0f : 1.0f) * bl[r];
                const float den = __shfl_down_sync(0xFFFFFFFFu, acc, 16);
                float v = 0.f;
                if (!role) v = st_tot[b][r] * acc * frcp(den);
                v += __shfl_xor_sync(0xFFFFFFFFu, v, 8);
                v += __shfl_xor_sync(0xFFFFFFFFu, v, 4);
                v += __shfl_xor_sync(0xFFFFFFFFu, v, 2);
                v += __shfl_xor_sync(0xFFFFFFFFu, v, 1);
                if (l == 0) out[b0 + b] = v;
            }
        }
    }
}

// ============================================================================
extern "C" void kernel_launch(void* const* d_in, const int* in_sizes, int n_in,
                              void* d_out, int out_size)
{
    (void)in_sizes; (void)n_in; (void)out_size;
    const int*   x_idx = (const int*)  d_in[0];
    const float* emb   = (const float*)d_in[1];
    const float* Wih   = (const float*)d_in[2];
    const float* Whh   = (const float*)d_in[3];
    const float* bih   = (const float*)d_in[4];
    const float* bhh   = (const float*)d_in[5];
    const float* Wf    = (const float*)d_in[6];
    const float* bf    = (const float*)d_in[7];
    const float* Wm    = (const float*)d_in[8];
    const float* bm    = (const float*)d_in[9];
    const float* Wl    = (const float*)d_in[10];
    const float* bl    = (const float*)d_in[11];
    float* out = (float*)d_out;

    k_prep <<<112, 256>>>(emb, Wih, bih, bhh, Whh, Wm);
    k_h0   <<<NE, 256>>>(Wf, bf);
    k_chain<<<BAT / 2, 512>>>(x_idx, bm, Wl, bl, out);
}